// round 1
// baseline (speedup 1.0000x reference)
#include <cuda_runtime.h>
#include <cstdint>

// ---------------------------------------------------------------------------
// GAT_37709812858998: 2-layer GAT (heads=1) + FC + BatchNorm + FC + log_softmax
// Strategy:
//   * eliminate h_dst GEMM: a_dst = x @ (W_dst @ att_dst)
//   * CSR-by-dst built once per call (reused by both layers), warp-per-node
//     aggregation with in-register softmax (no float atomics)
//   * fp32 SIMT GEMMs (64x128 / 64x64 tiles)
//   * fused BN-stats + fused head (fc2 + log_softmax) kernel
// ---------------------------------------------------------------------------

#define MAXN 100096
#define MAXE 1700160

__device__ float g_A[(size_t)MAXN * 128];     // h_src of current layer
__device__ float g_B[(size_t)MAXN * 128];     // layer output (h1 / h2)
__device__ float g_h3[(size_t)MAXN * 64];     // fc1 output
__device__ float g_asrc[MAXN];
__device__ float g_adst[MAXN];
__device__ float g_wda[256];
__device__ int   g_deg[MAXN];
__device__ int   g_off[MAXN];
__device__ int   g_cur[MAXN];
__device__ int   g_scan[MAXN];
__device__ int   g_bsum[256];
__device__ int   g_esrc[MAXE];
__device__ float g_bn[128];                   // [0:64) sum, [64:128) sumsq
__device__ float g_mu[64];
__device__ float g_rstd[64];
__device__ int   g_is64;

// ---------------------------------------------------------------------------
// dtype detection for edge_index (int64 vs int32 depending on JAX x64 config)
// ---------------------------------------------------------------------------
__global__ void k_detect(const void* ei, int N) {
    if (threadIdx.x == 0 && blockIdx.x == 0) {
        const long long* p = (const long long*)ei;
        int ok = 1;
        for (int i = 0; i < 64; i++) {
            long long v = p[i];
            if (v < 0 || v >= (long long)N) ok = 0;
        }
        g_is64 = ok;
    }
}

// ---------------------------------------------------------------------------
// CSR build: degree count -> scan -> scatter  (edges = edge_index ++ self-loops)
// ---------------------------------------------------------------------------
__global__ void k_zero_deg(int N) {
    int i = blockIdx.x * blockDim.x + threadIdx.x;
    if (i < N) g_deg[i] = 0;
}

__global__ void k_deg(const void* eiv, int E, int ET) {
    int i = blockIdx.x * blockDim.x + threadIdx.x;
    if (i >= ET) return;
    int dst;
    if (i >= E) dst = i - E;
    else if (g_is64) dst = (int)((const long long*)eiv)[E + i];
    else            dst = ((const int*)eiv)[E + i];
    atomicAdd(&g_deg[dst], 1);
}

__global__ void k_scan1(int N) {
    __shared__ int sh[1024];
    int i = blockIdx.x * 1024 + threadIdx.x;
    int v = (i < N) ? g_deg[i] : 0;
    sh[threadIdx.x] = v;
    __syncthreads();
    for (int o = 1; o < 1024; o <<= 1) {
        int t = (threadIdx.x >= o) ? sh[threadIdx.x - o] : 0;
        __syncthreads();
        sh[threadIdx.x] += t;
        __syncthreads();
    }
    if (i < N) g_scan[i] = sh[threadIdx.x];
    if (threadIdx.x == 1023) g_bsum[blockIdx.x] = sh[1023];
}

__global__ void k_scan2(int nb) {
    __shared__ int sh[128];
    int v = (threadIdx.x < nb) ? g_bsum[threadIdx.x] : 0;
    sh[threadIdx.x] = v;
    __syncthreads();
    for (int o = 1; o < 128; o <<= 1) {
        int t = (threadIdx.x >= o) ? sh[threadIdx.x - o] : 0;
        __syncthreads();
        sh[threadIdx.x] += t;
        __syncthreads();
    }
    if (threadIdx.x < nb) g_bsum[threadIdx.x] = sh[threadIdx.x] - v;  // exclusive
}

__global__ void k_scan3(int N) {
    int i = blockIdx.x * blockDim.x + threadIdx.x;
    if (i >= N) return;
    int o = g_scan[i] - g_deg[i] + g_bsum[i >> 10];
    g_off[i] = o;
    g_cur[i] = o;
}

__global__ void k_scatter(const void* eiv, int E, int ET) {
    int i = blockIdx.x * blockDim.x + threadIdx.x;
    if (i >= ET) return;
    int src, dst;
    if (i >= E) { src = i - E; dst = i - E; }
    else if (g_is64) {
        src = (int)((const long long*)eiv)[i];
        dst = (int)((const long long*)eiv)[E + i];
    } else {
        src = ((const int*)eiv)[i];
        dst = ((const int*)eiv)[E + i];
    }
    int pos = atomicAdd(&g_cur[dst], 1);
    g_esrc[pos] = src;
}

// ---------------------------------------------------------------------------
// wda[d] = dot(W_dst[d, :128], att_dst)
// ---------------------------------------------------------------------------
__global__ void k_wvec(const float* __restrict__ W, const float* __restrict__ att,
                       float* __restrict__ out) {
    int d = blockIdx.x;
    float v = W[d * 128 + threadIdx.x] * att[threadIdx.x];
    for (int o = 16; o > 0; o >>= 1) v += __shfl_xor_sync(0xffffffffu, v, o);
    __shared__ float sh[4];
    if ((threadIdx.x & 31) == 0) sh[threadIdx.x >> 5] = v;
    __syncthreads();
    if (threadIdx.x == 0) out[d] = sh[0] + sh[1] + sh[2] + sh[3];
}

// ---------------------------------------------------------------------------
// GEMM: C[N, ND] = X[N, KD] @ W[KD, ND], fp32. BM=64, BK=16, 256 threads.
// ---------------------------------------------------------------------------
template <int KD, int ND>
__global__ void __launch_bounds__(256) k_gemm(const float* __restrict__ X,
                                              const float* __restrict__ W,
                                              float* __restrict__ C, int N) {
    constexpr int TN = ND / 16;            // 8 (ND=128) or 4 (ND=64)
    __shared__ float Xs[16][68];           // transposed: Xs[k][m]
    __shared__ float Ws[16][ND + 4];
    int tid = threadIdx.x;
    int bm = blockIdx.x * 64;
    int trow = tid >> 4, tcol = tid & 15;
    float acc[4][TN];
#pragma unroll
    for (int i = 0; i < 4; i++)
#pragma unroll
        for (int j = 0; j < TN; j++) acc[i][j] = 0.f;

    int lxr = tid >> 2;
    int lxc = (tid & 3) * 4;

    for (int k0 = 0; k0 < KD; k0 += 16) {
        float4 xv = make_float4(0.f, 0.f, 0.f, 0.f);
        int gr = bm + lxr;
        if (gr < N) xv = *(const float4*)(X + (size_t)gr * KD + k0 + lxc);
        Xs[lxc + 0][lxr] = xv.x;
        Xs[lxc + 1][lxr] = xv.y;
        Xs[lxc + 2][lxr] = xv.z;
        Xs[lxc + 3][lxr] = xv.w;
#pragma unroll
        for (int i = tid; i < 16 * ND / 4; i += 256) {
            int r = i / (ND / 4);
            int c = (i % (ND / 4)) * 4;
            *(float4*)&Ws[r][c] = *(const float4*)(W + (size_t)(k0 + r) * ND + c);
        }
        __syncthreads();
#pragma unroll
        for (int kk = 0; kk < 16; kk++) {
            float4 a = *(const float4*)&Xs[kk][trow << 2];
            float a4[4] = {a.x, a.y, a.z, a.w};
            float b[TN];
#pragma unroll
            for (int j = 0; j < TN; j += 4) {
                float4 bv = *(const float4*)&Ws[kk][tcol * TN + j];
                b[j] = bv.x; b[j + 1] = bv.y; b[j + 2] = bv.z; b[j + 3] = bv.w;
            }
#pragma unroll
            for (int i = 0; i < 4; i++)
#pragma unroll
                for (int j = 0; j < TN; j++) acc[i][j] = fmaf(a4[i], b[j], acc[i][j]);
        }
        __syncthreads();
    }
#pragma unroll
    for (int i = 0; i < 4; i++) {
        int r = bm + trow * 4 + i;
        if (r < N) {
#pragma unroll
            for (int j = 0; j < TN; j += 4) {
                float4 v = make_float4(acc[i][j], acc[i][j + 1], acc[i][j + 2], acc[i][j + 3]);
                *(float4*)(C + (size_t)r * ND + tcol * TN + j) = v;
            }
        }
    }
}

// ---------------------------------------------------------------------------
// a_src[n] = h[n]·att (128);  a_dst[n] = xin[n]·wda (Kx). Warp per node.
// ---------------------------------------------------------------------------
__global__ void __launch_bounds__(256) k_attn(const float* __restrict__ hs,
                                              const float* __restrict__ xin, int Kx,
                                              const float* __restrict__ att,
                                              const float* __restrict__ wda,
                                              float* __restrict__ asrc,
                                              float* __restrict__ adst, int N) {
    int w = (blockIdx.x * 256 + threadIdx.x) >> 5;
    int lane = threadIdx.x & 31;
    if (w >= N) return;
    float4 h = *(const float4*)(hs + (size_t)w * 128 + lane * 4);
    float4 a = *(const float4*)(att + lane * 4);
    float s1 = h.x * a.x + h.y * a.y + h.z * a.z + h.w * a.w;
    float s2 = 0.f;
    for (int c = lane * 4; c < Kx; c += 128) {
        float4 xv = *(const float4*)(xin + (size_t)w * Kx + c);
        float4 wv = *(const float4*)(wda + c);
        s2 += xv.x * wv.x + xv.y * wv.y + xv.z * wv.z + xv.w * wv.w;
    }
    for (int o = 16; o > 0; o >>= 1) {
        s1 += __shfl_xor_sync(0xffffffffu, s1, o);
        s2 += __shfl_xor_sync(0xffffffffu, s2, o);
    }
    if (lane == 0) { asrc[w] = s1; adst[w] = s2; }
}

// ---------------------------------------------------------------------------
// Warp-per-node GAT aggregation: softmax over incoming edges, weighted sum of
// h_src rows, + bias, relu.  No atomics.
// ---------------------------------------------------------------------------
__global__ void __launch_bounds__(256) k_agg(const float* __restrict__ H,
                                             const float* __restrict__ asrc,
                                             const float* __restrict__ adst,
                                             const float* __restrict__ bias,
                                             float* __restrict__ out, int N) {
    int w = (blockIdx.x * 256 + threadIdx.x) >> 5;
    int lane = threadIdx.x & 31;
    if (w >= N) return;
    int st = g_off[w];
    int d = g_deg[w];
    float ad = adst[w];
    // pass 1: max over edges (lanes strided)
    float m = -1e30f;
    for (int j = lane; j < d; j += 32) {
        int s = g_esrc[st + j];
        float e = asrc[s] + ad;
        e = (e >= 0.f) ? e : 0.2f * e;
        m = fmaxf(m, e);
    }
    for (int o = 16; o > 0; o >>= 1) m = fmaxf(m, __shfl_xor_sync(0xffffffffu, m, o));
    // pass 2: edges sequential, lanes over 128 feature columns (4 each)
    float den = 0.f, ax = 0.f, ay = 0.f, az = 0.f, aw = 0.f;
#pragma unroll 4
    for (int j = 0; j < d; j++) {
        int s = g_esrc[st + j];
        float e = asrc[s] + ad;
        e = (e >= 0.f) ? e : 0.2f * e;
        float p = __expf(e - m);
        den += p;
        float4 h = *(const float4*)(H + (size_t)s * 128 + lane * 4);
        ax = fmaf(p, h.x, ax);
        ay = fmaf(p, h.y, ay);
        az = fmaf(p, h.z, az);
        aw = fmaf(p, h.w, aw);
    }
    float inv = 1.0f / den;
    float4 b = *(const float4*)(bias + lane * 4);
    float4 o4;
    o4.x = fmaxf(fmaf(ax, inv, b.x), 0.f);
    o4.y = fmaxf(fmaf(ay, inv, b.y), 0.f);
    o4.z = fmaf(az, inv, b.z); o4.z = fmaxf(o4.z, 0.f);
    o4.w = fmaxf(fmaf(aw, inv, b.w), 0.f);
    *(float4*)(out + (size_t)w * 128 + lane * 4) = o4;
}

// ---------------------------------------------------------------------------
// BN: add fc1 bias in-place + accumulate per-column sum/sumsq
// ---------------------------------------------------------------------------
__global__ void k_zero_bn() {
    if (threadIdx.x < 128) g_bn[threadIdx.x] = 0.f;
}

__global__ void __launch_bounds__(256) k_bstats(float* __restrict__ H3,
                                                const float* __restrict__ b, int N) {
    int c = threadIdx.x & 63;
    int rg = threadIdx.x >> 6;  // 0..3
    float bc = b[c];
    float s = 0.f, q = 0.f;
    for (int r = blockIdx.x * 4 + rg; r < N; r += gridDim.x * 4) {
        float v = H3[(size_t)r * 64 + c] + bc;
        H3[(size_t)r * 64 + c] = v;
        s += v;
        q += v * v;
    }
    __shared__ float ss[4][64], qq[4][64];
    ss[rg][c] = s;
    qq[rg][c] = q;
    __syncthreads();
    if (threadIdx.x < 64) {
        float S = ss[0][c] + ss[1][c] + ss[2][c] + ss[3][c];
        float Q = qq[0][c] + qq[1][c] + qq[2][c] + qq[3][c];
        atomicAdd(&g_bn[c], S);
        atomicAdd(&g_bn[64 + c], Q);
    }
}

__global__ void k_bnfinal(int N) {
    int c = threadIdx.x;
    float invN = 1.0f / (float)N;
    float m = g_bn[c] * invN;
    float v = g_bn[64 + c] * invN - m * m;
    g_mu[c] = m;
    g_rstd[c] = rsqrtf(v + 1e-5f);
}

// ---------------------------------------------------------------------------
// Head: normalize+relu, @fc2 (64x40), +bias, log_softmax.  Warp per row.
// ---------------------------------------------------------------------------
__global__ void __launch_bounds__(256) k_head(const float* __restrict__ H3,
                                              const float* __restrict__ W2,
                                              const float* __restrict__ b2,
                                              const float* __restrict__ gamma,
                                              const float* __restrict__ beta,
                                              float* __restrict__ out, int N) {
    __shared__ float Ws[64][40];
    __shared__ float cb[40], cg[64], cbt[64], cmu[64], crs[64];
    __shared__ float xs[8][64];
    int tid = threadIdx.x;
    for (int i = tid; i < 64 * 40; i += 256) Ws[i / 40][i % 40] = W2[i];
    if (tid < 40) cb[tid] = b2[tid];
    if (tid < 64) {
        cg[tid] = gamma[tid];
        cbt[tid] = beta[tid];
        cmu[tid] = g_mu[tid];
        crs[tid] = g_rstd[tid];
    }
    __syncthreads();
    int w = tid >> 5, lane = tid & 31;
    int row = blockIdx.x * 8 + w;
    if (row >= N) return;
    float v0 = H3[(size_t)row * 64 + lane];
    float v1 = H3[(size_t)row * 64 + 32 + lane];
    int l2 = 32 + lane;
    v0 = fmaxf((v0 - cmu[lane]) * crs[lane] * cg[lane] + cbt[lane], 0.f);
    v1 = fmaxf((v1 - cmu[l2]) * crs[l2] * cg[l2] + cbt[l2], 0.f);
    xs[w][lane] = v0;
    xs[w][l2] = v1;
    __syncwarp();
    float o0 = cb[lane];                        // lane < 40 always (lane <= 31)
    float o1 = (lane < 8) ? cb[32 + lane] : 0.f;
#pragma unroll
    for (int k = 0; k < 64; k++) {
        float xv = xs[w][k];
        o0 = fmaf(xv, Ws[k][lane], o0);
        if (lane < 8) o1 = fmaf(xv, Ws[k][32 + lane], o1);
    }
    float mx = (lane < 8) ? fmaxf(o0, o1) : o0;
    for (int o = 16; o > 0; o >>= 1) mx = fmaxf(mx, __shfl_xor_sync(0xffffffffu, mx, o));
    float s = expf(o0 - mx) + ((lane < 8) ? expf(o1 - mx) : 0.f);
    for (int o = 16; o > 0; o >>= 1) s += __shfl_xor_sync(0xffffffffu, s, o);
    float lse = mx + logf(s);
    out[(size_t)row * 40 + lane] = o0 - lse;
    if (lane < 8) out[(size_t)row * 40 + 32 + lane] = o1 - lse;
}

// ---------------------------------------------------------------------------
// Launch
// ---------------------------------------------------------------------------
extern "C" void kernel_launch(void* const* d_in, const int* in_sizes, int n_in,
                              void* d_out, int out_size) {
    const float* x        = (const float*)d_in[0];
    const void*  ei       = d_in[1];
    const float* W1_src   = (const float*)d_in[2];
    const float* W1_dst   = (const float*)d_in[3];
    const float* att1_src = (const float*)d_in[4];
    const float* att1_dst = (const float*)d_in[5];
    const float* b1       = (const float*)d_in[6];
    const float* W2_src   = (const float*)d_in[7];
    const float* W2_dst   = (const float*)d_in[8];
    const float* att2_src = (const float*)d_in[9];
    const float* att2_dst = (const float*)d_in[10];
    const float* b2       = (const float*)d_in[11];
    const float* fc1_w    = (const float*)d_in[12];
    const float* fc1_b    = (const float*)d_in[13];
    const float* gamma    = (const float*)d_in[14];
    const float* beta     = (const float*)d_in[15];
    const float* fc2_w    = (const float*)d_in[16];
    const float* fc2_b    = (const float*)d_in[17];
    float* out = (float*)d_out;

    int N = in_sizes[0] / 256;
    int E = in_sizes[1] / 2;
    int ET = E + N;

    float *pA, *pB, *pH3, *pAsrc, *pAdst, *pWda;
    cudaGetSymbolAddress((void**)&pA, g_A);
    cudaGetSymbolAddress((void**)&pB, g_B);
    cudaGetSymbolAddress((void**)&pH3, g_h3);
    cudaGetSymbolAddress((void**)&pAsrc, g_asrc);
    cudaGetSymbolAddress((void**)&pAdst, g_adst);
    cudaGetSymbolAddress((void**)&pWda, g_wda);

    int nb = (N + 1023) / 1024;

    // ---- CSR build (shared by both layers) ----
    k_detect<<<1, 32>>>(ei, N);
    k_zero_deg<<<(N + 255) / 256, 256>>>(N);
    k_deg<<<(ET + 255) / 256, 256>>>(ei, E, ET);
    k_scan1<<<nb, 1024>>>(N);
    k_scan2<<<1, 128>>>(nb);
    k_scan3<<<(N + 255) / 256, 256>>>(N);
    k_scatter<<<(ET + 255) / 256, 256>>>(ei, E, ET);

    int gN64 = (N + 63) / 64;
    int gW = (N + 7) / 8;

    // ---- Layer 1 ----
    k_wvec<<<256, 128>>>(W1_dst, att1_dst, pWda);
    k_gemm<256, 128><<<gN64, 256>>>(x, W1_src, pA, N);
    k_attn<<<gW, 256>>>(pA, x, 256, att1_src, pWda, pAsrc, pAdst, N);
    k_agg<<<gW, 256>>>(pA, pAsrc, pAdst, b1, pB, N);

    // ---- Layer 2 ----
    k_wvec<<<128, 128>>>(W2_dst, att2_dst, pWda);
    k_gemm<128, 128><<<gN64, 256>>>(pB, W2_src, pA, N);
    k_attn<<<gW, 256>>>(pA, pB, 128, att2_src, pWda, pAsrc, pAdst, N);
    k_agg<<<gW, 256>>>(pA, pAsrc, pAdst, b2, pB, N);

    // ---- Head ----
    k_zero_bn<<<1, 128>>>();
    k_gemm<128, 64><<<gN64, 256>>>(pB, fc1_w, pH3, N);
    k_bstats<<<512, 256>>>(pH3, fc1_b, N);
    k_bnfinal<<<1, 64>>>(N);
    k_head<<<gW, 256>>>(pH3, fc2_w, fc2_b, gamma, beta, out, N);
}

// round 3
// speedup vs baseline: 1.2709x; 1.2709x over previous
#include <cuda_runtime.h>
#include <cstdint>

// ---------------------------------------------------------------------------
// GAT_37709812858998: 2-layer GAT + FC/BN/FC/log_softmax
// R3: mma.sync tf32 (m16n8k8) GEMMs — tcgen05 is unavailable (PTX target
//     sm_103 lacks the 'a' feature set). Fragment-packed SMEM staging.
//     CSR aggregation identical to the passing R1 kernel.
// ---------------------------------------------------------------------------

#define MAXN 100096
#define MAXE 1700160

__device__ float g_A[(size_t)MAXN * 128];
__device__ float g_B[(size_t)MAXN * 128];
__device__ float g_h3[(size_t)MAXN * 64];
__device__ float g_asrc[MAXN];
__device__ float g_adst[MAXN];
__device__ float g_wda[256];
__device__ int   g_deg[MAXN];
__device__ int   g_off[MAXN];
__device__ int   g_cur[MAXN];
__device__ int   g_scan[MAXN];
__device__ int   g_bsum[256];
__device__ int   g_esrc[MAXE];
__device__ float g_bn[128];
__device__ float g_mu[64];
__device__ float g_rstd[64];
__device__ int   g_is64;

__device__ __forceinline__ float to_tf32f(float f) {
    uint32_t r;
    asm("cvt.rna.tf32.f32 %0, %1;" : "=r"(r) : "f"(f));
    return __uint_as_float(r);
}

// ---------------------------------------------------------------------------
// dtype detection for edge_index (int64 vs int32)
// ---------------------------------------------------------------------------
__global__ void k_detect(const void* ei, int N) {
    if (threadIdx.x == 0 && blockIdx.x == 0) {
        const long long* p = (const long long*)ei;
        int ok = 1;
        for (int i = 0; i < 64; i++) {
            long long v = p[i];
            if (v < 0 || v >= (long long)N) ok = 0;
        }
        g_is64 = ok;
    }
}

// ---------------------------------------------------------------------------
// CSR build
// ---------------------------------------------------------------------------
__global__ void k_zero_deg(int N) {
    int i = blockIdx.x * blockDim.x + threadIdx.x;
    if (i < N) g_deg[i] = 0;
}
__global__ void k_deg(const void* eiv, int E, int ET) {
    int i = blockIdx.x * blockDim.x + threadIdx.x;
    if (i >= ET) return;
    int dst;
    if (i >= E) dst = i - E;
    else if (g_is64) dst = (int)((const long long*)eiv)[E + i];
    else            dst = ((const int*)eiv)[E + i];
    atomicAdd(&g_deg[dst], 1);
}
__global__ void k_scan1(int N) {
    __shared__ int sh[1024];
    int i = blockIdx.x * 1024 + threadIdx.x;
    int v = (i < N) ? g_deg[i] : 0;
    sh[threadIdx.x] = v;
    __syncthreads();
    for (int o = 1; o < 1024; o <<= 1) {
        int t = (threadIdx.x >= o) ? sh[threadIdx.x - o] : 0;
        __syncthreads();
        sh[threadIdx.x] += t;
        __syncthreads();
    }
    if (i < N) g_scan[i] = sh[threadIdx.x];
    if (threadIdx.x == 1023) g_bsum[blockIdx.x] = sh[1023];
}
__global__ void k_scan2(int nb) {
    __shared__ int sh[128];
    int v = (threadIdx.x < nb) ? g_bsum[threadIdx.x] : 0;
    sh[threadIdx.x] = v;
    __syncthreads();
    for (int o = 1; o < 128; o <<= 1) {
        int t = (threadIdx.x >= o) ? sh[threadIdx.x - o] : 0;
        __syncthreads();
        sh[threadIdx.x] += t;
        __syncthreads();
    }
    if (threadIdx.x < nb) g_bsum[threadIdx.x] = sh[threadIdx.x] - v;
}
__global__ void k_scan3(int N) {
    int i = blockIdx.x * blockDim.x + threadIdx.x;
    if (i >= N) return;
    int o = g_scan[i] - g_deg[i] + g_bsum[i >> 10];
    g_off[i] = o;
    g_cur[i] = o;
}
__global__ void k_scatter(const void* eiv, int E, int ET) {
    int i = blockIdx.x * blockDim.x + threadIdx.x;
    if (i >= ET) return;
    int src, dst;
    if (i >= E) { src = i - E; dst = i - E; }
    else if (g_is64) {
        src = (int)((const long long*)eiv)[i];
        dst = (int)((const long long*)eiv)[E + i];
    } else {
        src = ((const int*)eiv)[i];
        dst = ((const int*)eiv)[E + i];
    }
    int pos = atomicAdd(&g_cur[dst], 1);
    g_esrc[pos] = src;
}

// ---------------------------------------------------------------------------
// wda[d] = dot(W_dst[d, :128], att_dst)
// ---------------------------------------------------------------------------
__global__ void k_wvec(const float* __restrict__ W, const float* __restrict__ att,
                       float* __restrict__ out) {
    int d = blockIdx.x;
    float v = W[d * 128 + threadIdx.x] * att[threadIdx.x];
    for (int o = 16; o > 0; o >>= 1) v += __shfl_xor_sync(0xffffffffu, v, o);
    __shared__ float sh[4];
    if ((threadIdx.x & 31) == 0) sh[threadIdx.x >> 5] = v;
    __syncthreads();
    if (threadIdx.x == 0) out[d] = sh[0] + sh[1] + sh[2] + sh[3];
}

// ---------------------------------------------------------------------------
// GEMM via mma.sync m16n8k8 tf32: C[N, ND] = X[N, KD] @ W[KD, ND]
// CTA: 128 x ND, K chunk 32. Fragment-packed SMEM staging.
// ---------------------------------------------------------------------------
template <int KD, int ND>
__global__ void __launch_bounds__(256, 2) k_gemm_mma(const float* __restrict__ X,
                                                     const float* __restrict__ W,
                                                     float* __restrict__ C, int Nn) {
    constexpr int NT = ND / 8;         // total n8-tiles
    constexpr int WN = ND / 32;        // warps along N (4 or 2)
    constexpr int WM = 8 / WN;         // warps along M (2 or 4)
    constexpr int MTw = (128 / WM) / 16;  // m16-tiles per warp (4 or 2)
    constexpr int ASK = 8 * 32 * 4;       // 1024 floats per sk slice
    constexpr int APS = ASK + 36;         // padded stride
    constexpr int BSK = NT * 32 * 2;      // floats per sk slice
    constexpr int BPS = BSK + 36;

    __shared__ float As[4 * APS];
    __shared__ float Bs[4 * BPS];

    int tid = threadIdx.x;
    int lane = tid & 31;
    int w = tid >> 5;
    int wm = w % WM;
    int wn = w / WM;
    int g = lane >> 2;
    int t = lane & 3;
    int bm = blockIdx.x * 128;

    float acc[MTw][4][4];
#pragma unroll
    for (int i = 0; i < MTw; i++)
#pragma unroll
        for (int j = 0; j < 4; j++)
#pragma unroll
            for (int k = 0; k < 4; k++) acc[i][j][k] = 0.f;

    for (int k0 = 0; k0 < KD; k0 += 32) {
        // ---- stage A (128 x 32) into fragment-packed layout ----
#pragma unroll
        for (int it = 0; it < 4; it++) {
            int idx = tid + it * 256;
            int r = idx >> 3;
            int cq = (idx & 7) << 2;            // k col base (mult of 4)
            float4 v = make_float4(0.f, 0.f, 0.f, 0.f);
            if (bm + r < Nn) v = *(const float4*)(X + (size_t)(bm + r) * KD + k0 + cq);
            int sk = cq >> 3;
            int j = ((cq & 7) ? 2 : 0) + ((r >> 3) & 1);
            int mt = r >> 4;
            int lb = (r & 7) << 2;
            float* dst = &As[sk * APS + mt * 128 + j];
            dst[(lb + 0) * 4] = to_tf32f(v.x);
            dst[(lb + 1) * 4] = to_tf32f(v.y);
            dst[(lb + 2) * 4] = to_tf32f(v.z);
            dst[(lb + 3) * 4] = to_tf32f(v.w);
        }
        // ---- stage B (32 x ND) into fragment-packed layout ----
#pragma unroll
        for (int it = 0; it < ND / 32; it++) {
            int idx = tid + it * 256;
            int kr = idx / (ND / 4);
            int nb = (idx % (ND / 4)) * 4;
            float4 v = *(const float4*)(W + (size_t)(k0 + kr) * ND + nb);
            int sk = kr >> 3;
            int kk = kr & 7;
            int tt = kk & 3;
            int j = kk >> 2;
            float vv[4] = {v.x, v.y, v.z, v.w};
#pragma unroll
            for (int e = 0; e < 4; e++) {
                int n = nb + e;
                int nt = n >> 3;
                int gg = n & 7;
                Bs[sk * BPS + nt * 64 + (gg * 4 + tt) * 2 + j] = to_tf32f(vv[e]);
            }
        }
        __syncthreads();
        // ---- compute ----
#pragma unroll
        for (int sk = 0; sk < 4; sk++) {
            uint32_t a[MTw][4];
#pragma unroll
            for (int mt = 0; mt < MTw; mt++) {
                float4 av = *(const float4*)&As[sk * APS + (wm * MTw + mt) * 128 + lane * 4];
                a[mt][0] = __float_as_uint(av.x);
                a[mt][1] = __float_as_uint(av.y);
                a[mt][2] = __float_as_uint(av.z);
                a[mt][3] = __float_as_uint(av.w);
            }
            uint32_t b[4][2];
#pragma unroll
            for (int nt = 0; nt < 4; nt++) {
                float2 bv = *(const float2*)&Bs[sk * BPS + (wn * 4 + nt) * 64 + lane * 2];
                b[nt][0] = __float_as_uint(bv.x);
                b[nt][1] = __float_as_uint(bv.y);
            }
#pragma unroll
            for (int mt = 0; mt < MTw; mt++)
#pragma unroll
                for (int nt = 0; nt < 4; nt++) {
                    asm volatile(
                        "mma.sync.aligned.m16n8k8.row.col.f32.tf32.tf32.f32 "
                        "{%0,%1,%2,%3}, {%4,%5,%6,%7}, {%8,%9}, {%0,%1,%2,%3};"
                        : "+f"(acc[mt][nt][0]), "+f"(acc[mt][nt][1]),
                          "+f"(acc[mt][nt][2]), "+f"(acc[mt][nt][3])
                        : "r"(a[mt][0]), "r"(a[mt][1]), "r"(a[mt][2]), "r"(a[mt][3]),
                          "r"(b[nt][0]), "r"(b[nt][1]));
                }
        }
        __syncthreads();
    }
    // ---- epilogue ----
#pragma unroll
    for (int mt = 0; mt < MTw; mt++) {
        int r0 = bm + (wm * MTw + mt) * 16 + g;
        int r1 = r0 + 8;
#pragma unroll
        for (int nt = 0; nt < 4; nt++) {
            int c0 = (wn * 4 + nt) * 8 + t * 2;
            if (r0 < Nn)
                *(float2*)(C + (size_t)r0 * ND + c0) = make_float2(acc[mt][nt][0], acc[mt][nt][1]);
            if (r1 < Nn)
                *(float2*)(C + (size_t)r1 * ND + c0) = make_float2(acc[mt][nt][2], acc[mt][nt][3]);
        }
    }
}

// ---------------------------------------------------------------------------
// a_src[n] = h[n]·att (128);  a_dst[n] = xin[n]·wda (Kx). Warp per node.
// ---------------------------------------------------------------------------
__global__ void __launch_bounds__(256) k_attn(const float* __restrict__ hs,
                                              const float* __restrict__ xin, int Kx,
                                              const float* __restrict__ att,
                                              const float* __restrict__ wda,
                                              float* __restrict__ asrc,
                                              float* __restrict__ adst, int N) {
    int w = (blockIdx.x * 256 + threadIdx.x) >> 5;
    int lane = threadIdx.x & 31;
    if (w >= N) return;
    float4 h = *(const float4*)(hs + (size_t)w * 128 + lane * 4);
    float4 a = *(const float4*)(att + lane * 4);
    float s1 = h.x * a.x + h.y * a.y + h.z * a.z + h.w * a.w;
    float s2 = 0.f;
    for (int c = lane * 4; c < Kx; c += 128) {
        float4 xv = *(const float4*)(xin + (size_t)w * Kx + c);
        float4 wv = *(const float4*)(wda + c);
        s2 += xv.x * wv.x + xv.y * wv.y + xv.z * wv.z + xv.w * wv.w;
    }
    for (int o = 16; o > 0; o >>= 1) {
        s1 += __shfl_xor_sync(0xffffffffu, s1, o);
        s2 += __shfl_xor_sync(0xffffffffu, s2, o);
    }
    if (lane == 0) { asrc[w] = s1; adst[w] = s2; }
}

// ---------------------------------------------------------------------------
// Warp-per-node GAT aggregation (softmax + weighted sum + bias + relu)
// ---------------------------------------------------------------------------
__global__ void __launch_bounds__(256) k_agg(const float* __restrict__ H,
                                             const float* __restrict__ asrc,
                                             const float* __restrict__ adst,
                                             const float* __restrict__ bias,
                                             float* __restrict__ out, int N) {
    int w = (blockIdx.x * 256 + threadIdx.x) >> 5;
    int lane = threadIdx.x & 31;
    if (w >= N) return;
    int st = g_off[w];
    int d = g_deg[w];
    float ad = adst[w];
    float m = -1e30f;
    for (int j = lane; j < d; j += 32) {
        int s = g_esrc[st + j];
        float e = asrc[s] + ad;
        e = (e >= 0.f) ? e : 0.2f * e;
        m = fmaxf(m, e);
    }
    for (int o = 16; o > 0; o >>= 1) m = fmaxf(m, __shfl_xor_sync(0xffffffffu, m, o));
    float den = 0.f, ax = 0.f, ay = 0.f, az = 0.f, aw = 0.f;
#pragma unroll 4
    for (int j = 0; j < d; j++) {
        int s = g_esrc[st + j];
        float e = asrc[s] + ad;
        e = (e >= 0.f) ? e : 0.2f * e;
        float p = __expf(e - m);
        den += p;
        float4 h = *(const float4*)(H + (size_t)s * 128 + lane * 4);
        ax = fmaf(p, h.x, ax);
        ay = fmaf(p, h.y, ay);
        az = fmaf(p, h.z, az);
        aw = fmaf(p, h.w, aw);
    }
    float inv = 1.0f / den;
    float4 b = *(const float4*)(bias + lane * 4);
    float4 o4;
    o4.x = fmaxf(fmaf(ax, inv, b.x), 0.f);
    o4.y = fmaxf(fmaf(ay, inv, b.y), 0.f);
    o4.z = fmaxf(fmaf(az, inv, b.z), 0.f);
    o4.w = fmaxf(fmaf(aw, inv, b.w), 0.f);
    *(float4*)(out + (size_t)w * 128 + lane * 4) = o4;
}

// ---------------------------------------------------------------------------
// BN stats + final
// ---------------------------------------------------------------------------
__global__ void k_zero_bn() {
    if (threadIdx.x < 128) g_bn[threadIdx.x] = 0.f;
}
__global__ void __launch_bounds__(256) k_bstats(float* __restrict__ H3,
                                                const float* __restrict__ b, int N) {
    int c = threadIdx.x & 63;
    int rg = threadIdx.x >> 6;
    float bc = b[c];
    float s = 0.f, q = 0.f;
    for (int r = blockIdx.x * 4 + rg; r < N; r += gridDim.x * 4) {
        float v = H3[(size_t)r * 64 + c] + bc;
        H3[(size_t)r * 64 + c] = v;
        s += v;
        q += v * v;
    }
    __shared__ float ss[4][64], qq[4][64];
    ss[rg][c] = s;
    qq[rg][c] = q;
    __syncthreads();
    if (threadIdx.x < 64) {
        float S = ss[0][c] + ss[1][c] + ss[2][c] + ss[3][c];
        float Q = qq[0][c] + qq[1][c] + qq[2][c] + qq[3][c];
        atomicAdd(&g_bn[c], S);
        atomicAdd(&g_bn[64 + c], Q);
    }
}
__global__ void k_bnfinal(int N) {
    int c = threadIdx.x;
    float invN = 1.0f / (float)N;
    float m = g_bn[c] * invN;
    float v = g_bn[64 + c] * invN - m * m;
    g_mu[c] = m;
    g_rstd[c] = rsqrtf(v + 1e-5f);
}

// ---------------------------------------------------------------------------
// Head: BN-normalize + relu + fc2 (64x40) + log_softmax. Warp per row.
// ---------------------------------------------------------------------------
__global__ void __launch_bounds__(256) k_head(const float* __restrict__ H3,
                                              const float* __restrict__ W2,
                                              const float* __restrict__ b2,
                                              const float* __restrict__ gamma,
                                              const float* __restrict__ beta,
                                              float* __restrict__ out, int N) {
    __shared__ float Ws[64][40];
    __shared__ float cb[40], cg[64], cbt[64], cmu[64], crs[64];
    __shared__ float xs[8][64];
    int tid = threadIdx.x;
    for (int i = tid; i < 64 * 40; i += 256) Ws[i / 40][i % 40] = W2[i];
    if (tid < 40) cb[tid] = b2[tid];
    if (tid < 64) {
        cg[tid] = gamma[tid];
        cbt[tid] = beta[tid];
        cmu[tid] = g_mu[tid];
        crs[tid] = g_rstd[tid];
    }
    __syncthreads();
    int w = tid >> 5, lane = tid & 31;
    int row = blockIdx.x * 8 + w;
    if (row >= N) return;
    float v0 = H3[(size_t)row * 64 + lane];
    float v1 = H3[(size_t)row * 64 + 32 + lane];
    int l2 = 32 + lane;
    v0 = fmaxf((v0 - cmu[lane]) * crs[lane] * cg[lane] + cbt[lane], 0.f);
    v1 = fmaxf((v1 - cmu[l2]) * crs[l2] * cg[l2] + cbt[l2], 0.f);
    xs[w][lane] = v0;
    xs[w][l2] = v1;
    __syncwarp();
    float o0 = cb[lane];
    float o1 = (lane < 8) ? cb[32 + lane] : 0.f;
#pragma unroll
    for (int k = 0; k < 64; k++) {
        float xv = xs[w][k];
        o0 = fmaf(xv, Ws[k][lane], o0);
        if (lane < 8) o1 = fmaf(xv, Ws[k][32 + lane], o1);
    }
    float mx = (lane < 8) ? fmaxf(o0, o1) : o0;
    for (int o = 16; o > 0; o >>= 1) mx = fmaxf(mx, __shfl_xor_sync(0xffffffffu, mx, o));
    float s = expf(o0 - mx) + ((lane < 8) ? expf(o1 - mx) : 0.f);
    for (int o = 16; o > 0; o >>= 1) s += __shfl_xor_sync(0xffffffffu, s, o);
    float lse = mx + logf(s);
    out[(size_t)row * 40 + lane] = o0 - lse;
    if (lane < 8) out[(size_t)row * 40 + 32 + lane] = o1 - lse;
}

// ---------------------------------------------------------------------------
// Launch
// ---------------------------------------------------------------------------
extern "C" void kernel_launch(void* const* d_in, const int* in_sizes, int n_in,
                              void* d_out, int out_size) {
    const float* x        = (const float*)d_in[0];
    const void*  ei       = d_in[1];
    const float* W1_src   = (const float*)d_in[2];
    const float* W1_dst   = (const float*)d_in[3];
    const float* att1_src = (const float*)d_in[4];
    const float* att1_dst = (const float*)d_in[5];
    const float* b1       = (const float*)d_in[6];
    const float* W2_src   = (const float*)d_in[7];
    const float* W2_dst   = (const float*)d_in[8];
    const float* att2_src = (const float*)d_in[9];
    const float* att2_dst = (const float*)d_in[10];
    const float* b2       = (const float*)d_in[11];
    const float* fc1_w    = (const float*)d_in[12];
    const float* fc1_b    = (const float*)d_in[13];
    const float* gamma    = (const float*)d_in[14];
    const float* beta     = (const float*)d_in[15];
    const float* fc2_w    = (const float*)d_in[16];
    const float* fc2_b    = (const float*)d_in[17];
    float* out = (float*)d_out;

    int N = in_sizes[0] / 256;
    int E = in_sizes[1] / 2;
    int ET = E + N;

    float *pA, *pB, *pH3, *pAsrc, *pAdst, *pWda;
    cudaGetSymbolAddress((void**)&pA, g_A);
    cudaGetSymbolAddress((void**)&pB, g_B);
    cudaGetSymbolAddress((void**)&pH3, g_h3);
    cudaGetSymbolAddress((void**)&pAsrc, g_asrc);
    cudaGetSymbolAddress((void**)&pAdst, g_adst);
    cudaGetSymbolAddress((void**)&pWda, g_wda);

    int nb = (N + 1023) / 1024;

    // ---- CSR build ----
    k_detect<<<1, 32>>>(ei, N);
    k_zero_deg<<<(N + 255) / 256, 256>>>(N);
    k_deg<<<(ET + 255) / 256, 256>>>(ei, E, ET);
    k_scan1<<<nb, 1024>>>(N);
    k_scan2<<<1, 128>>>(nb);
    k_scan3<<<(N + 255) / 256, 256>>>(N);
    k_scatter<<<(ET + 255) / 256, 256>>>(ei, E, ET);

    int gM = (N + 127) / 128;
    int gW = (N + 7) / 8;

    // ---- Layer 1 ----
    k_wvec<<<256, 128>>>(W1_dst, att1_dst, pWda);
    k_gemm_mma<256, 128><<<gM, 256>>>(x, W1_src, pA, N);
    k_attn<<<gW, 256>>>(pA, x, 256, att1_src, pWda, pAsrc, pAdst, N);
    k_agg<<<gW, 256>>>(pA, pAsrc, pAdst, b1, pB, N);

    // ---- Layer 2 ----
    k_wvec<<<128, 128>>>(W2_dst, att2_dst, pWda);
    k_gemm_mma<128, 128><<<gM, 256>>>(pB, W2_src, pA, N);
    k_attn<<<gW, 256>>>(pA, pB, 128, att2_src, pWda, pAsrc, pAdst, N);
    k_agg<<<gW, 256>>>(pA, pAsrc, pAdst, b2, pB, N);

    // ---- Head ----
    k_zero_bn<<<1, 128>>>();
    k_gemm_mma<128, 64><<<gM, 256>>>(pB, fc1_w, pH3, N);
    k_bstats<<<512, 256>>>(pH3, fc1_b, N);
    k_bnfinal<<<1, 64>>>(N);
    k_head<<<gW, 256>>>(pH3, fc2_w, fc2_b, gamma, beta, out, N);
}

// round 4
// speedup vs baseline: 1.3719x; 1.0794x over previous
#include <cuda_runtime.h>
#include <cuda_fp16.h>
#include <cstdint>

// ---------------------------------------------------------------------------
// GAT_37709812858998: 2-layer GAT + FC/BN/FC/log_softmax
// R4: fp16 h_src storage, a_src/a_dst fused into GEMM, single-pass softmax agg
// ---------------------------------------------------------------------------

#define MAXN 100096
#define MAXE 1700160

__device__ float g_A[(size_t)MAXN * 128];   // h_src (as __half, aliased)
__device__ float g_B[(size_t)MAXN * 128];   // layer output (fp32)
__device__ float g_h3[(size_t)MAXN * 64];
__device__ float g_asrc[MAXN];
__device__ float g_adst[MAXN];
__device__ float g_wda[256];
__device__ int   g_deg[MAXN];
__device__ int   g_off[MAXN];
__device__ int   g_cur[MAXN];
__device__ int   g_scan[MAXN];
__device__ int   g_bsum[256];
__device__ int   g_esrc[MAXE];
__device__ float g_bn[128];
__device__ float g_mu[64];
__device__ float g_rstd[64];
__device__ int   g_is64;

__device__ __forceinline__ float to_tf32f(float f) {
    uint32_t r;
    asm("cvt.rna.tf32.f32 %0, %1;" : "=r"(r) : "f"(f));
    return __uint_as_float(r);
}

// ---------------------------------------------------------------------------
__global__ void k_detect(const void* ei, int N) {
    if (threadIdx.x == 0 && blockIdx.x == 0) {
        const long long* p = (const long long*)ei;
        int ok = 1;
        for (int i = 0; i < 64; i++) {
            long long v = p[i];
            if (v < 0 || v >= (long long)N) ok = 0;
        }
        g_is64 = ok;
    }
}

// ---------------------------------------------------------------------------
// CSR build
// ---------------------------------------------------------------------------
__global__ void k_zero_deg(int N) {
    int i = blockIdx.x * blockDim.x + threadIdx.x;
    if (i < N) g_deg[i] = 0;
}
__global__ void k_deg(const void* eiv, int E, int ET) {
    int i = blockIdx.x * blockDim.x + threadIdx.x;
    if (i >= ET) return;
    int dst;
    if (i >= E) dst = i - E;
    else if (g_is64) dst = (int)((const long long*)eiv)[E + i];
    else            dst = ((const int*)eiv)[E + i];
    atomicAdd(&g_deg[dst], 1);
}
__global__ void k_scan1(int N) {
    __shared__ int sh[1024];
    int i = blockIdx.x * 1024 + threadIdx.x;
    int v = (i < N) ? g_deg[i] : 0;
    sh[threadIdx.x] = v;
    __syncthreads();
    for (int o = 1; o < 1024; o <<= 1) {
        int t = (threadIdx.x >= o) ? sh[threadIdx.x - o] : 0;
        __syncthreads();
        sh[threadIdx.x] += t;
        __syncthreads();
    }
    if (i < N) g_scan[i] = sh[threadIdx.x];
    if (threadIdx.x == 1023) g_bsum[blockIdx.x] = sh[1023];
}
__global__ void k_scan2(int nb) {
    __shared__ int sh[128];
    int v = (threadIdx.x < nb) ? g_bsum[threadIdx.x] : 0;
    sh[threadIdx.x] = v;
    __syncthreads();
    for (int o = 1; o < 128; o <<= 1) {
        int t = (threadIdx.x >= o) ? sh[threadIdx.x - o] : 0;
        __syncthreads();
        sh[threadIdx.x] += t;
        __syncthreads();
    }
    if (threadIdx.x < nb) g_bsum[threadIdx.x] = sh[threadIdx.x] - v;
}
__global__ void k_scan3(int N) {
    int i = blockIdx.x * blockDim.x + threadIdx.x;
    if (i >= N) return;
    int o = g_scan[i] - g_deg[i] + g_bsum[i >> 10];
    g_off[i] = o;
    g_cur[i] = o;
}
__global__ void k_scatter(const void* eiv, int E, int ET) {
    int i = blockIdx.x * blockDim.x + threadIdx.x;
    if (i >= ET) return;
    int src, dst;
    if (i >= E) { src = i - E; dst = i - E; }
    else if (g_is64) {
        src = (int)((const long long*)eiv)[i];
        dst = (int)((const long long*)eiv)[E + i];
    } else {
        src = ((const int*)eiv)[i];
        dst = ((const int*)eiv)[E + i];
    }
    int pos = atomicAdd(&g_cur[dst], 1);
    g_esrc[pos] = src;
}

// ---------------------------------------------------------------------------
// wda[d] = dot(W_dst[d, :128], att_dst)
// ---------------------------------------------------------------------------
__global__ void k_wvec(const float* __restrict__ W, const float* __restrict__ att,
                       float* __restrict__ out) {
    int d = blockIdx.x;
    float v = W[d * 128 + threadIdx.x] * att[threadIdx.x];
    for (int o = 16; o > 0; o >>= 1) v += __shfl_xor_sync(0xffffffffu, v, o);
    __shared__ float sh[4];
    if ((threadIdx.x & 31) == 0) sh[threadIdx.x >> 5] = v;
    __syncthreads();
    if (threadIdx.x == 0) out[d] = sh[0] + sh[1] + sh[2] + sh[3];
}

// ---------------------------------------------------------------------------
// GEMM via mma.sync m16n8k8 tf32: C = X[N,KD] @ W[KD,ND].  CTA 128 x ND.
// HOUT: write C as fp16 (h_src path).  Fused: asrc = C·att, adst = X·wda.
// ---------------------------------------------------------------------------
template <int KD, int ND, bool HOUT>
__global__ void __launch_bounds__(256, 2) k_gemm_mma(const float* __restrict__ X,
                                                     const float* __restrict__ W,
                                                     float* __restrict__ Cf,
                                                     __half* __restrict__ Ch,
                                                     const float* __restrict__ att,
                                                     float* __restrict__ asrc,
                                                     const float* __restrict__ wda,
                                                     float* __restrict__ adst,
                                                     int Nn) {
    constexpr int NT = ND / 8;
    constexpr int WN = ND / 32;
    constexpr int WM = 8 / WN;
    constexpr int MTw = (128 / WM) / 16;
    constexpr int ASK = 8 * 32 * 4;
    constexpr int APS = ASK + 36;
    constexpr int BSK = NT * 32 * 2;
    constexpr int BPS = BSK + 36;

    __shared__ float As[4 * APS];
    __shared__ float Bs[4 * BPS];
    __shared__ float att_s[ND];
    __shared__ float wda_s[KD];
    __shared__ float asum[128];
    __shared__ float dsum[128];

    int tid = threadIdx.x;
    int lane = tid & 31;
    int w = tid >> 5;
    int wm = w % WM;
    int wn = w / WM;
    int g = lane >> 2;
    int t = lane & 3;
    int bm = blockIdx.x * 128;

    if (att != nullptr)
        for (int i = tid; i < ND; i += 256) att_s[i] = att[i];
    if (wda != nullptr)
        for (int i = tid; i < KD; i += 256) wda_s[i] = wda[i];
    if (tid < 128) { asum[tid] = 0.f; dsum[tid] = 0.f; }
    __syncthreads();

    float acc[MTw][4][4];
#pragma unroll
    for (int i = 0; i < MTw; i++)
#pragma unroll
        for (int j = 0; j < 4; j++)
#pragma unroll
            for (int k = 0; k < 4; k++) acc[i][j][k] = 0.f;

    for (int k0 = 0; k0 < KD; k0 += 32) {
        // ---- stage A (128 x 32), fused x·wda partial ----
#pragma unroll
        for (int it = 0; it < 4; it++) {
            int idx = tid + it * 256;
            int r = idx >> 3;
            int cq = (idx & 7) << 2;
            float4 v = make_float4(0.f, 0.f, 0.f, 0.f);
            if (bm + r < Nn) v = *(const float4*)(X + (size_t)(bm + r) * KD + k0 + cq);
            if (wda != nullptr) {
                float p = v.x * wda_s[k0 + cq] + v.y * wda_s[k0 + cq + 1] +
                          v.z * wda_s[k0 + cq + 2] + v.w * wda_s[k0 + cq + 3];
                p += __shfl_xor_sync(0xffffffffu, p, 1);
                p += __shfl_xor_sync(0xffffffffu, p, 2);
                p += __shfl_xor_sync(0xffffffffu, p, 4);
                if ((lane & 7) == 0) atomicAdd(&dsum[r], p);
            }
            int sk = cq >> 3;
            int j = ((cq & 7) ? 2 : 0) + ((r >> 3) & 1);
            int mt = r >> 4;
            int lb = (r & 7) << 2;
            float* dst = &As[sk * APS + mt * 128 + j];
            dst[(lb + 0) * 4] = to_tf32f(v.x);
            dst[(lb + 1) * 4] = to_tf32f(v.y);
            dst[(lb + 2) * 4] = to_tf32f(v.z);
            dst[(lb + 3) * 4] = to_tf32f(v.w);
        }
        // ---- stage B (32 x ND) ----
#pragma unroll
        for (int it = 0; it < ND / 32; it++) {
            int idx = tid + it * 256;
            int kr = idx / (ND / 4);
            int nb = (idx % (ND / 4)) * 4;
            float4 v = *(const float4*)(W + (size_t)(k0 + kr) * ND + nb);
            int sk = kr >> 3;
            int kk = kr & 7;
            int tt = kk & 3;
            int j = kk >> 2;
            float vv[4] = {v.x, v.y, v.z, v.w};
#pragma unroll
            for (int e = 0; e < 4; e++) {
                int n = nb + e;
                int nt = n >> 3;
                int gg = n & 7;
                Bs[sk * BPS + nt * 64 + (gg * 4 + tt) * 2 + j] = to_tf32f(vv[e]);
            }
        }
        __syncthreads();
        // ---- compute ----
#pragma unroll
        for (int sk = 0; sk < 4; sk++) {
            uint32_t a[MTw][4];
#pragma unroll
            for (int mt = 0; mt < MTw; mt++) {
                float4 av = *(const float4*)&As[sk * APS + (wm * MTw + mt) * 128 + lane * 4];
                a[mt][0] = __float_as_uint(av.x);
                a[mt][1] = __float_as_uint(av.y);
                a[mt][2] = __float_as_uint(av.z);
                a[mt][3] = __float_as_uint(av.w);
            }
            uint32_t b[4][2];
#pragma unroll
            for (int nt = 0; nt < 4; nt++) {
                float2 bv = *(const float2*)&Bs[sk * BPS + (wn * 4 + nt) * 64 + lane * 2];
                b[nt][0] = __float_as_uint(bv.x);
                b[nt][1] = __float_as_uint(bv.y);
            }
#pragma unroll
            for (int mt = 0; mt < MTw; mt++)
#pragma unroll
                for (int nt = 0; nt < 4; nt++) {
                    asm volatile(
                        "mma.sync.aligned.m16n8k8.row.col.f32.tf32.tf32.f32 "
                        "{%0,%1,%2,%3}, {%4,%5,%6,%7}, {%8,%9}, {%0,%1,%2,%3};"
                        : "+f"(acc[mt][nt][0]), "+f"(acc[mt][nt][1]),
                          "+f"(acc[mt][nt][2]), "+f"(acc[mt][nt][3])
                        : "r"(a[mt][0]), "r"(a[mt][1]), "r"(a[mt][2]), "r"(a[mt][3]),
                          "r"(b[nt][0]), "r"(b[nt][1]));
                }
        }
        __syncthreads();
    }
    // ---- fused a_src partials ----
    if (att != nullptr) {
#pragma unroll
        for (int mt = 0; mt < MTw; mt++) {
            float s0 = 0.f, s1 = 0.f;
#pragma unroll
            for (int nt = 0; nt < 4; nt++) {
                int c0 = (wn * 4 + nt) * 8 + t * 2;
                float a0 = att_s[c0], a1 = att_s[c0 + 1];
                s0 += acc[mt][nt][0] * a0 + acc[mt][nt][1] * a1;
                s1 += acc[mt][nt][2] * a0 + acc[mt][nt][3] * a1;
            }
            s0 += __shfl_xor_sync(0xffffffffu, s0, 1);
            s0 += __shfl_xor_sync(0xffffffffu, s0, 2);
            s1 += __shfl_xor_sync(0xffffffffu, s1, 1);
            s1 += __shfl_xor_sync(0xffffffffu, s1, 2);
            if (t == 0) {
                int rl = (wm * MTw + mt) * 16 + g;
                atomicAdd(&asum[rl], s0);
                atomicAdd(&asum[rl + 8], s1);
            }
        }
    }
    // ---- store C ----
#pragma unroll
    for (int mt = 0; mt < MTw; mt++) {
        int r0 = bm + (wm * MTw + mt) * 16 + g;
        int r1 = r0 + 8;
#pragma unroll
        for (int nt = 0; nt < 4; nt++) {
            int c0 = (wn * 4 + nt) * 8 + t * 2;
            if (HOUT) {
                if (r0 < Nn)
                    *(__half2*)(Ch + (size_t)r0 * ND + c0) =
                        __floats2half2_rn(acc[mt][nt][0], acc[mt][nt][1]);
                if (r1 < Nn)
                    *(__half2*)(Ch + (size_t)r1 * ND + c0) =
                        __floats2half2_rn(acc[mt][nt][2], acc[mt][nt][3]);
            } else {
                if (r0 < Nn)
                    *(float2*)(Cf + (size_t)r0 * ND + c0) =
                        make_float2(acc[mt][nt][0], acc[mt][nt][1]);
                if (r1 < Nn)
                    *(float2*)(Cf + (size_t)r1 * ND + c0) =
                        make_float2(acc[mt][nt][2], acc[mt][nt][3]);
            }
        }
    }
    if (att != nullptr || wda != nullptr) {
        __syncthreads();
        if (tid < 128 && bm + tid < Nn) {
            if (att != nullptr) asrc[bm + tid] = asum[tid];
            if (wda != nullptr) adst[bm + tid] = dsum[tid];
        }
    }
}

// ---------------------------------------------------------------------------
// Warp-per-node aggregation, single pass (no max — e is bounded), fp16 H.
// ---------------------------------------------------------------------------
__global__ void __launch_bounds__(256) k_agg(const __half* __restrict__ H,
                                             const float* __restrict__ asrc,
                                             const float* __restrict__ adst,
                                             const float* __restrict__ bias,
                                             float* __restrict__ out, int N) {
    int w = (blockIdx.x * 256 + threadIdx.x) >> 5;
    int lane = threadIdx.x & 31;
    if (w >= N) return;
    int st = g_off[w];
    int d = g_deg[w];
    float ad = adst[w];
    float den = 0.f, ax = 0.f, ay = 0.f, az = 0.f, aw = 0.f;
#pragma unroll 4
    for (int j = 0; j < d; j++) {
        int s = g_esrc[st + j];
        float e = asrc[s] + ad;
        e = (e >= 0.f) ? e : 0.2f * e;
        float p = __expf(e);
        den += p;
        uint2 hv = *(const uint2*)(H + (size_t)s * 128 + lane * 4);
        float2 f0 = __half22float2(*(const __half2*)&hv.x);
        float2 f1 = __half22float2(*(const __half2*)&hv.y);
        ax = fmaf(p, f0.x, ax);
        ay = fmaf(p, f0.y, ay);
        az = fmaf(p, f1.x, az);
        aw = fmaf(p, f1.y, aw);
    }
    float inv = 1.0f / den;
    float4 b = *(const float4*)(bias + lane * 4);
    float4 o4;
    o4.x = fmaxf(fmaf(ax, inv, b.x), 0.f);
    o4.y = fmaxf(fmaf(ay, inv, b.y), 0.f);
    o4.z = fmaxf(fmaf(az, inv, b.z), 0.f);
    o4.w = fmaxf(fmaf(aw, inv, b.w), 0.f);
    *(float4*)(out + (size_t)w * 128 + lane * 4) = o4;
}

// ---------------------------------------------------------------------------
// BN stats + final
// ---------------------------------------------------------------------------
__global__ void k_zero_bn() {
    if (threadIdx.x < 128) g_bn[threadIdx.x] = 0.f;
}
__global__ void __launch_bounds__(256) k_bstats(float* __restrict__ H3,
                                                const float* __restrict__ b, int N) {
    int c = threadIdx.x & 63;
    int rg = threadIdx.x >> 6;
    float bc = b[c];
    float s = 0.f, q = 0.f;
    for (int r = blockIdx.x * 4 + rg; r < N; r += gridDim.x * 4) {
        float v = H3[(size_t)r * 64 + c] + bc;
        H3[(size_t)r * 64 + c] = v;
        s += v;
        q += v * v;
    }
    __shared__ float ss[4][64], qq[4][64];
    ss[rg][c] = s;
    qq[rg][c] = q;
    __syncthreads();
    if (threadIdx.x < 64) {
        float S = ss[0][c] + ss[1][c] + ss[2][c] + ss[3][c];
        float Q = qq[0][c] + qq[1][c] + qq[2][c] + qq[3][c];
        atomicAdd(&g_bn[c], S);
        atomicAdd(&g_bn[64 + c], Q);
    }
}
__global__ void k_bnfinal(int N) {
    int c = threadIdx.x;
    float invN = 1.0f / (float)N;
    float m = g_bn[c] * invN;
    float v = g_bn[64 + c] * invN - m * m;
    g_mu[c] = m;
    g_rstd[c] = rsqrtf(v + 1e-5f);
}

// ---------------------------------------------------------------------------
// Head: BN-normalize + relu + fc2 (64x40) + log_softmax. Warp per row.
// ---------------------------------------------------------------------------
__global__ void __launch_bounds__(256) k_head(const float* __restrict__ H3,
                                              const float* __restrict__ W2,
                                              const float* __restrict__ b2,
                                              const float* __restrict__ gamma,
                                              const float* __restrict__ beta,
                                              float* __restrict__ out, int N) {
    __shared__ float Ws[64][40];
    __shared__ float cb[40], cg[64], cbt[64], cmu[64], crs[64];
    __shared__ float xs[8][64];
    int tid = threadIdx.x;
    for (int i = tid; i < 64 * 40; i += 256) Ws[i / 40][i % 40] = W2[i];
    if (tid < 40) cb[tid] = b2[tid];
    if (tid < 64) {
        cg[tid] = gamma[tid];
        cbt[tid] = beta[tid];
        cmu[tid] = g_mu[tid];
        crs[tid] = g_rstd[tid];
    }
    __syncthreads();
    int w = tid >> 5, lane = tid & 31;
    int row = blockIdx.x * 8 + w;
    if (row >= N) return;
    float v0 = H3[(size_t)row * 64 + lane];
    float v1 = H3[(size_t)row * 64 + 32 + lane];
    int l2 = 32 + lane;
    v0 = fmaxf((v0 - cmu[lane]) * crs[lane] * cg[lane] + cbt[lane], 0.f);
    v1 = fmaxf((v1 - cmu[l2]) * crs[l2] * cg[l2] + cbt[l2], 0.f);
    xs[w][lane] = v0;
    xs[w][l2] = v1;
    __syncwarp();
    float o0 = cb[lane];
    float o1 = (lane < 8) ? cb[32 + lane] : 0.f;
#pragma unroll
    for (int k = 0; k < 64; k++) {
        float xv = xs[w][k];
        o0 = fmaf(xv, Ws[k][lane], o0);
        if (lane < 8) o1 = fmaf(xv, Ws[k][32 + lane], o1);
    }
    float mx = (lane < 8) ? fmaxf(o0, o1) : o0;
    for (int o = 16; o > 0; o >>= 1) mx = fmaxf(mx, __shfl_xor_sync(0xffffffffu, mx, o));
    float s = expf(o0 - mx) + ((lane < 8) ? expf(o1 - mx) : 0.f);
    for (int o = 16; o > 0; o >>= 1) s += __shfl_xor_sync(0xffffffffu, s, o);
    float lse = mx + logf(s);
    out[(size_t)row * 40 + lane] = o0 - lse;
    if (lane < 8) out[(size_t)row * 40 + 32 + lane] = o1 - lse;
}

// ---------------------------------------------------------------------------
// Launch
// ---------------------------------------------------------------------------
extern "C" void kernel_launch(void* const* d_in, const int* in_sizes, int n_in,
                              void* d_out, int out_size) {
    const float* x        = (const float*)d_in[0];
    const void*  ei       = d_in[1];
    const float* W1_src   = (const float*)d_in[2];
    const float* W1_dst   = (const float*)d_in[3];
    const float* att1_src = (const float*)d_in[4];
    const float* att1_dst = (const float*)d_in[5];
    const float* b1       = (const float*)d_in[6];
    const float* W2_src   = (const float*)d_in[7];
    const float* W2_dst   = (const float*)d_in[8];
    const float* att2_src = (const float*)d_in[9];
    const float* att2_dst = (const float*)d_in[10];
    const float* b2       = (const float*)d_in[11];
    const float* fc1_w    = (const float*)d_in[12];
    const float* fc1_b    = (const float*)d_in[13];
    const float* gamma    = (const float*)d_in[14];
    const float* beta     = (const float*)d_in[15];
    const float* fc2_w    = (const float*)d_in[16];
    const float* fc2_b    = (const float*)d_in[17];
    float* out = (float*)d_out;

    int N = in_sizes[0] / 256;
    int E = in_sizes[1] / 2;
    int ET = E + N;

    float *pA, *pB, *pH3, *pAsrc, *pAdst, *pWda;
    cudaGetSymbolAddress((void**)&pA, g_A);
    cudaGetSymbolAddress((void**)&pB, g_B);
    cudaGetSymbolAddress((void**)&pH3, g_h3);
    cudaGetSymbolAddress((void**)&pAsrc, g_asrc);
    cudaGetSymbolAddress((void**)&pAdst, g_adst);
    cudaGetSymbolAddress((void**)&pWda, g_wda);
    __half* pAh = (__half*)pA;

    int nb = (N + 1023) / 1024;

    // ---- CSR build ----
    k_detect<<<1, 32>>>(ei, N);
    k_zero_deg<<<(N + 255) / 256, 256>>>(N);
    k_deg<<<(ET + 255) / 256, 256>>>(ei, E, ET);
    k_scan1<<<nb, 1024>>>(N);
    k_scan2<<<1, 128>>>(nb);
    k_scan3<<<(N + 255) / 256, 256>>>(N);
    k_scatter<<<(ET + 255) / 256, 256>>>(ei, E, ET);

    int gM = (N + 127) / 128;
    int gW = (N + 7) / 8;

    // ---- Layer 1 ----
    k_wvec<<<256, 128>>>(W1_dst, att1_dst, pWda);
    k_gemm_mma<256, 128, true><<<gM, 256>>>(x, W1_src, nullptr, pAh,
                                            att1_src, pAsrc, pWda, pAdst, N);
    k_agg<<<gW, 256>>>(pAh, pAsrc, pAdst, b1, pB, N);

    // ---- Layer 2 ----
    k_wvec<<<128, 128>>>(W2_dst, att2_dst, pWda);
    k_gemm_mma<128, 128, true><<<gM, 256>>>(pB, W2_src, nullptr, pAh,
                                            att2_src, pAsrc, pWda, pAdst, N);
    k_agg<<<gW, 256>>>(pAh, pAsrc, pAdst, b2, pB, N);

    // ---- Head ----
    k_zero_bn<<<1, 128>>>();
    k_gemm_mma<128, 64, false><<<gM, 256>>>(pB, fc1_w, pH3, nullptr,
                                            nullptr, nullptr, nullptr, nullptr, N);
    k_bstats<<<512, 256>>>(pH3, fc1_b, N);
    k_bnfinal<<<1, 64>>>(N);
    k_head<<<gW, 256>>>(pH3, fc2_w, fc2_b, gamma, beta, out, N);
}